// round 1
// baseline (speedup 1.0000x reference)
#include <cuda_runtime.h>

// SyntacticGCN fused kernel for GB300 (sm_103a)
// B=16, S=128, M=128, D=256, H=256
//
// out[row, j] = leaky_relu( sum_k hidden[row,k] * W[k,j] + b[j] ), slope 0.01
// hidden[row] = concat( sum_m src[row,m,:], (sum_m neigh[row,m,:]) / max(count_valid,1) )
// valid[m] = any(neigh[row,m,:] != 0)

#define BB 16
#define SS 128
#define MM 128
#define DD 256
#define HH 256
#define NROWS (BB * SS)   // 2048
#define RPC 8             // rows per CTA
#define NW 8              // warps per CTA
#define NTHREADS 256

__global__ __launch_bounds__(NTHREADS, 2)
void gcn_fused_kernel(const float* __restrict__ src,
                      const float* __restrict__ ngh,
                      const float* __restrict__ Wm,   // [2D, H] row-major
                      const float* __restrict__ bm,   // [H]
                      float* __restrict__ out)        // [NROWS, H]
{
    __shared__ float part[NW][2 * DD];   // warp partials: [w][0..255]=src, [w][256..511]=neigh (16 KB)
    __shared__ int   cnts[NW];
    __shared__ float hid[RPC][2 * DD];   // concat hidden rows (16 KB)

    const int tid  = threadIdx.x;
    const int warp = tid >> 5;
    const int lane = tid & 31;
    const int row0 = blockIdx.x * RPC;

    // ---------------- Phase 1: per-row reductions ----------------
    for (int r = 0; r < RPC; ++r) {
        const int row = row0 + r;
        const float4* sp = (const float4*)(src + (size_t)row * MM * DD);
        const float4* np = (const float4*)(ngh + (size_t)row * MM * DD);

        float4 sa0 = make_float4(0.f, 0.f, 0.f, 0.f);
        float4 sa1 = make_float4(0.f, 0.f, 0.f, 0.f);
        float4 na0 = make_float4(0.f, 0.f, 0.f, 0.f);
        float4 na1 = make_float4(0.f, 0.f, 0.f, 0.f);
        int cnt = 0;

        // each warp handles m = warp, warp+8, ... (16 rows); each lane owns 8 columns
        #pragma unroll 4
        for (int m = warp; m < MM; m += NW) {
            const float4* rs = sp + m * (DD / 4) + lane * 2;
            const float4* rn = np + m * (DD / 4) + lane * 2;
            float4 s0 = __ldg(rs);
            float4 s1 = __ldg(rs + 1);
            float4 n0 = __ldg(rn);
            float4 n1 = __ldg(rn + 1);

            sa0.x += s0.x; sa0.y += s0.y; sa0.z += s0.z; sa0.w += s0.w;
            sa1.x += s1.x; sa1.y += s1.y; sa1.z += s1.z; sa1.w += s1.w;
            na0.x += n0.x; na0.y += n0.y; na0.z += n0.z; na0.w += n0.w;
            na1.x += n1.x; na1.y += n1.y; na1.z += n1.z; na1.w += n1.w;

            bool nz = (n0.x != 0.f) | (n0.y != 0.f) | (n0.z != 0.f) | (n0.w != 0.f) |
                      (n1.x != 0.f) | (n1.y != 0.f) | (n1.z != 0.f) | (n1.w != 0.f);
            if (__any_sync(0xffffffffu, nz)) cnt++;
        }

        // stage warp partials to shared (128-bit stores, conflict-free)
        float4* ps = (float4*)&part[warp][0];
        ps[lane * 2]     = sa0;
        ps[lane * 2 + 1] = sa1;
        float4* pn = (float4*)&part[warp][DD];
        pn[lane * 2]     = na0;
        pn[lane * 2 + 1] = na1;
        if (lane == 0) cnts[warp] = cnt;
        __syncthreads();

        // cross-warp reduce: thread t owns column t of src-sum and neigh-sum
        float ssum = 0.f, nsum = 0.f;
        #pragma unroll
        for (int w = 0; w < NW; ++w) {
            ssum += part[w][tid];
            nsum += part[w][DD + tid];
        }
        int ctot = 0;
        #pragma unroll
        for (int w = 0; w < NW; ++w) ctot += cnts[w];
        float inv = 1.0f / fmaxf((float)ctot, 1.0f);

        hid[r][tid]      = ssum;
        hid[r][DD + tid] = nsum * inv;
        __syncthreads();   // protect part[] reuse next iteration
    }

    // ---------------- Phase 2: GEMM + bias + leaky_relu ----------------
    // thread j = output column; accumulate all 8 rows against W column j
    const int j = tid;
    float acc[RPC];
    const float bj = __ldg(bm + j);
    #pragma unroll
    for (int r = 0; r < RPC; ++r) acc[r] = bj;

    const float4* h4 = (const float4*)(&hid[0][0]);   // [RPC][128] float4
    #pragma unroll 2
    for (int k = 0; k < 2 * DD; k += 4) {
        float w0 = __ldg(Wm + (size_t)(k + 0) * HH + j);
        float w1 = __ldg(Wm + (size_t)(k + 1) * HH + j);
        float w2 = __ldg(Wm + (size_t)(k + 2) * HH + j);
        float w3 = __ldg(Wm + (size_t)(k + 3) * HH + j);
        const int ki = k >> 2;
        #pragma unroll
        for (int r = 0; r < RPC; ++r) {
            float4 h = h4[r * (2 * DD / 4) + ki];   // smem broadcast
            acc[r] = fmaf(h.x, w0, acc[r]);
            acc[r] = fmaf(h.y, w1, acc[r]);
            acc[r] = fmaf(h.z, w2, acc[r]);
            acc[r] = fmaf(h.w, w3, acc[r]);
        }
    }

    #pragma unroll
    for (int r = 0; r < RPC; ++r) {
        float v = acc[r];
        out[(size_t)(row0 + r) * HH + j] = (v > 0.f) ? v : 0.01f * v;
    }
}

extern "C" void kernel_launch(void* const* d_in, const int* in_sizes, int n_in,
                              void* d_out, int out_size)
{
    const float* src = (const float*)d_in[0];   // [B,S,M,D]
    const float* ngh = (const float*)d_in[1];   // [B,S,M,D]
    const float* Wm  = (const float*)d_in[2];   // [2D,H]
    const float* bm  = (const float*)d_in[3];   // [H]
    float* out = (float*)d_out;                 // [B*S, H]

    gcn_fused_kernel<<<NROWS / RPC, NTHREADS>>>(src, ngh, Wm, bm, out);
}